// round 4
// baseline (speedup 1.0000x reference)
#include <cuda_runtime.h>
#include <cuda_bf16.h>
#include <stdint.h>
#include <math.h>

// ---------------- problem constants ----------------
#define V_  32000
#define D_  512
#define L_  6
#define FF_ 2048
#define T_  2048
#define B_  2
#define S_  8
#define DS_ 32
#define K_  15

#define BT_ (B_ * T_)          // 4096 tokens
#define NC_ 32                 // scan chunks
#define TC_ (T_ / NC_)         // 64 steps per chunk

// ---------------- device scratch (no allocations allowed) ----------------
// fp32 buffers
__device__ float d_X  [BT_ * D_];
__device__ float d_HN [BT_ * D_];        // fp32 norm out (story-memory branch only)
__device__ float d_GV [BT_ * 2 * D_];
__device__ float d_G  [BT_ * S_];
__device__ float d_RQ [BT_ * S_];
__device__ float d_V  [BT_ * DS_];
__device__ float d_MS [BT_ * S_ * DS_];
__device__ float d_UPc[BT_ * 2 * FF_];   // fused FFN gate|up output (N=4096)
__device__ float d_MEM[B_ * S_ * DS_];
__device__ float d_CHA[B_ * S_ * NC_];
__device__ float d_CHB[B_ * S_ * DS_ * NC_];
__device__ float d_CST[B_ * S_ * DS_ * NC_];

// split-bf16 packed operands: layout [row][KB blocks][16 words], block = k16:
// words 0..7 = hi pairs (k even low16, k odd high16), words 8..15 = lo pairs.
__device__ unsigned d_HN2[BT_ * D_];             // activations, K=512
__device__ unsigned d_CG2[BT_ * D_];             // K=512
__device__ unsigned d_RF2[BT_ * S_ * DS_];       // K=256
__device__ unsigned d_UP2[BT_ * FF_];            // K=2048
// weights (pre-converted once per launch)
__device__ unsigned d_WMU[L_ * 2 * D_ * D_];     // (1024,512) per layer
__device__ unsigned d_WMD[L_ * D_ * D_];         // (512,512)
__device__ unsigned d_WRO[L_ * D_ * S_ * DS_];   // (512,256)
__device__ unsigned d_WFF[L_ * 2 * FF_ * D_];    // (4096,512): rows 0..2047=Wgf, 2048..4095=Wuf
__device__ unsigned d_WOF[L_ * D_ * FF_];        // (512,2048)
__device__ unsigned d_WEM[V_ * D_];              // (32000,512)

// ---------------- bf16 split helpers ----------------
__device__ __forceinline__ unsigned bfhi_bits(float x) {
    unsigned u = __float_as_uint(x);
    return (u + 0x7fffu + ((u >> 16) & 1u)) & 0xffff0000u;   // RNE to bf16, as fp32 bits
}

__device__ __forceinline__ void split_pack(float x, float y, unsigned& hi, unsigned& lo) {
    unsigned hx = bfhi_bits(x), hy = bfhi_bits(y);
    float lx = x - __uint_as_float(hx);
    float ly = y - __uint_as_float(hy);
    unsigned lhx = bfhi_bits(lx), lhy = bfhi_bits(ly);
    hi = (hx >> 16) | (hy & 0xffff0000u);
    lo = (lhx >> 16) | (lhy & 0xffff0000u);
}

__device__ __forceinline__ void mma_bf16(float* c, const unsigned* a, unsigned b0, unsigned b1) {
    asm volatile(
        "mma.sync.aligned.m16n8k16.row.col.f32.bf16.bf16.f32 "
        "{%0,%1,%2,%3}, {%4,%5,%6,%7}, {%8,%9}, {%0,%1,%2,%3};"
        : "+f"(c[0]), "+f"(c[1]), "+f"(c[2]), "+f"(c[3])
        : "r"(a[0]), "r"(a[1]), "r"(a[2]), "r"(a[3]), "r"(b0), "r"(b1));
}

// ---------------- weight/operand converter ----------------
// src: fp32 [nRows][K]; dst packed split layout; dst row = (n/group)*dstride + dbase + n%group
__global__ __launch_bounds__(256) void convert_split_kernel(
    const float* __restrict__ src, unsigned* __restrict__ dst,
    int nRows, int K, int group, int dstride, int dbase)
{
    int kp2 = K >> 1;
    int idx = blockIdx.x * 256 + threadIdx.x;
    if (idx >= nRows * kp2) return;
    int n = idx / kp2, kp = idx - n * kp2;
    float x = src[(size_t)n * K + 2 * kp];
    float y = src[(size_t)n * K + 2 * kp + 1];
    unsigned hi, lo;
    split_pack(x, y, hi, lo);
    int dn = (n / group) * dstride + dbase + (n % group);
    size_t base = (((size_t)dn * (K >> 4) + (kp >> 3)) << 4) + (kp & 7);
    dst[base] = hi;
    dst[base + 8] = lo;
}

// ---------------- split-bf16 tensor-core GEMM: C[M,N] = A @ W^T (+R) ----------------
// A, W pre-split/packed. 128x128 tile, 8 warps (2x4), 64x32 warp tile, k-step 16,
// double-buffered smem, 3-term bf16 MMA (hi*hi + lo*hi + hi*lo).
#define ST_ 20   // smem row stride in words; (20*g + k) mod 32 is a permutation
template<bool RES>
__global__ __launch_bounds__(256) void bsgemm_kernel(
    const unsigned* __restrict__ A, const unsigned* __restrict__ W,
    const float* __restrict__ R, float* __restrict__ C,
    int M, int N, int KB)
{
    __shared__ unsigned SA[2][128 * ST_];
    __shared__ unsigned SB[2][128 * ST_];

    const int tid  = threadIdx.x;
    const int wid  = tid >> 5, lane = tid & 31;
    const int grp  = lane >> 2, kin = lane & 3;
    const int wm   = (wid & 1) * 64, wn = (wid >> 1) * 32;
    const int lr   = tid >> 1;          // 0..127
    const int h4   = (tid & 1) * 8;     // 0 or 8

    const unsigned* Ag = A + (((size_t)(blockIdx.y * 128 + lr) * KB) << 4) + h4;
    const unsigned* Wg = W + (((size_t)(blockIdx.x * 128 + lr) * KB) << 4) + h4;

    float acc[4][4][4];
#pragma unroll
    for (int i = 0; i < 4; i++)
#pragma unroll
        for (int j = 0; j < 4; j++)
#pragma unroll
            for (int r = 0; r < 4; r++) acc[i][j][r] = 0.f;

    // prologue: block 0 -> stage 0
    {
        uint4 a0 = *reinterpret_cast<const uint4*>(Ag);
        uint4 a1 = *reinterpret_cast<const uint4*>(Ag + 4);
        uint4 b0 = *reinterpret_cast<const uint4*>(Wg);
        uint4 b1 = *reinterpret_cast<const uint4*>(Wg + 4);
        *reinterpret_cast<uint4*>(&SA[0][lr * ST_ + h4])     = a0;
        *reinterpret_cast<uint4*>(&SA[0][lr * ST_ + h4 + 4]) = a1;
        *reinterpret_cast<uint4*>(&SB[0][lr * ST_ + h4])     = b0;
        *reinterpret_cast<uint4*>(&SB[0][lr * ST_ + h4 + 4]) = b1;
    }
    __syncthreads();

    for (int kt = 0; kt < KB; kt++) {
        const int cur = kt & 1;
        const bool more = (kt + 1 < KB);
        uint4 na0, na1, nb0, nb1;
        if (more) {
            const unsigned* ap = Ag + ((size_t)(kt + 1) << 4);
            const unsigned* wp = Wg + ((size_t)(kt + 1) << 4);
            na0 = *reinterpret_cast<const uint4*>(ap);
            na1 = *reinterpret_cast<const uint4*>(ap + 4);
            nb0 = *reinterpret_cast<const uint4*>(wp);
            nb1 = *reinterpret_cast<const uint4*>(wp + 4);
        }

        const unsigned* sA = &SA[cur][0];
        const unsigned* sB = &SB[cur][0];
        unsigned ah[4][4], al[4][4];
#pragma unroll
        for (int i = 0; i < 4; i++) {
            const int r0 = (wm + i * 16 + grp) * ST_;
            const int r1 = r0 + 8 * ST_;
            ah[i][0] = sA[r0 + kin];         ah[i][1] = sA[r1 + kin];
            ah[i][2] = sA[r0 + kin + 4];     ah[i][3] = sA[r1 + kin + 4];
            al[i][0] = sA[r0 + 8 + kin];     al[i][1] = sA[r1 + 8 + kin];
            al[i][2] = sA[r0 + 8 + kin + 4]; al[i][3] = sA[r1 + 8 + kin + 4];
        }
#pragma unroll
        for (int j = 0; j < 4; j++) {
            const int c0 = (wn + j * 8 + grp) * ST_;
            const unsigned bh0 = sB[c0 + kin],     bh1 = sB[c0 + kin + 4];
            const unsigned bl0 = sB[c0 + 8 + kin], bl1 = sB[c0 + 8 + kin + 4];
#pragma unroll
            for (int i = 0; i < 4; i++) {
                mma_bf16(acc[i][j], ah[i], bh0, bh1);
                mma_bf16(acc[i][j], al[i], bh0, bh1);
                mma_bf16(acc[i][j], ah[i], bl0, bl1);
            }
        }
        if (more) {
            unsigned* da = &SA[cur ^ 1][lr * ST_ + h4];
            unsigned* db = &SB[cur ^ 1][lr * ST_ + h4];
            *reinterpret_cast<uint4*>(da)     = na0;
            *reinterpret_cast<uint4*>(da + 4) = na1;
            *reinterpret_cast<uint4*>(db)     = nb0;
            *reinterpret_cast<uint4*>(db + 4) = nb1;
        }
        __syncthreads();
    }

    // epilogue
    const int row0 = blockIdx.y * 128 + wm + grp;
    const int col0 = blockIdx.x * 128 + wn + 2 * kin;
#pragma unroll
    for (int i = 0; i < 4; i++) {
#pragma unroll
        for (int j = 0; j < 4; j++) {
            const size_t o0 = (size_t)(row0 + i * 16) * N + col0 + j * 8;
            const size_t o1 = (size_t)(row0 + i * 16 + 8) * N + col0 + j * 8;
            float2 v0 = make_float2(acc[i][j][0], acc[i][j][1]);
            float2 v1 = make_float2(acc[i][j][2], acc[i][j][3]);
            if (RES) {
                float2 r0 = *reinterpret_cast<const float2*>(R + o0);
                float2 r1 = *reinterpret_cast<const float2*>(R + o1);
                v0.x += r0.x; v0.y += r0.y;
                v1.x += r1.x; v1.y += r1.y;
            }
            *reinterpret_cast<float2*>(C + o0) = v0;
            *reinterpret_cast<float2*>(C + o1) = v1;
        }
    }
}

// ---------------- embed gather + rmsnorm(ln_in) -> fp32 X ----------------
__global__ __launch_bounds__(256) void embed_norm_kernel(
    const int* __restrict__ tokens, const float* __restrict__ embed,
    const float* __restrict__ w, float* __restrict__ out)
{
    const int bt = blockIdx.x;
    const int tid = threadIdx.x;
    const int tok = tokens[bt];
    const float* row = embed + (size_t)tok * D_;
    float x0 = row[tid], x1 = row[tid + 256];
    __shared__ float red[256];
    red[tid] = x0 * x0 + x1 * x1;
    __syncthreads();
    for (int s = 128; s > 0; s >>= 1) {
        if (tid < s) red[tid] += red[tid + s];
        __syncthreads();
    }
    float scale = rsqrtf(red[0] / (float)D_ + 1e-6f);
    out[bt * D_ + tid]       = x0 * scale * w[tid];
    out[bt * D_ + tid + 256] = x1 * scale * w[tid + 256];
}

// ---------------- rmsnorm -> fp32 (story-memory branch) ----------------
__global__ __launch_bounds__(256) void rmsnorm_kernel(
    const float* __restrict__ X, const float* __restrict__ w, float* __restrict__ O)
{
    const int bt = blockIdx.x;
    const int tid = threadIdx.x;
    float x0 = X[bt * D_ + tid], x1 = X[bt * D_ + tid + 256];
    __shared__ float red[256];
    red[tid] = x0 * x0 + x1 * x1;
    __syncthreads();
    for (int s = 128; s > 0; s >>= 1) {
        if (tid < s) red[tid] += red[tid + s];
        __syncthreads();
    }
    float scale = rsqrtf(red[0] / (float)D_ + 1e-6f);
    O[bt * D_ + tid]       = x0 * scale * w[tid];
    O[bt * D_ + tid + 256] = x1 * scale * w[tid + 256];
}

// ---------------- rmsnorm -> split-packed (GEMM A operand) ----------------
__global__ __launch_bounds__(256) void rmsnorm_split_kernel(
    const float* __restrict__ X, const float* __restrict__ w, unsigned* __restrict__ O)
{
    const int bt = blockIdx.x;
    const int t = threadIdx.x;   // one thread per element pair
    float x0 = X[(size_t)bt * D_ + 2 * t];
    float x1 = X[(size_t)bt * D_ + 2 * t + 1];
    __shared__ float red[256];
    red[t] = x0 * x0 + x1 * x1;
    __syncthreads();
    for (int s = 128; s > 0; s >>= 1) {
        if (t < s) red[t] += red[t + s];
        __syncthreads();
    }
    float sc = rsqrtf(red[0] / (float)D_ + 1e-6f);
    float y0 = x0 * sc * w[2 * t], y1 = x1 * sc * w[2 * t + 1];
    unsigned hi, lo;
    split_pack(y0, y1, hi, lo);
    size_t base = (((size_t)bt * (D_ / 16) + (t >> 3)) << 4) + (t & 7);
    O[base] = hi; O[base + 8] = lo;
}

// ---------------- causal depthwise conv + gate -> split-packed ----------------
__global__ __launch_bounds__(256) void conv_gate_split_kernel(
    const float* __restrict__ GV, const float* __restrict__ cw, unsigned* __restrict__ CG2)
{
    const int idx = blockIdx.x * 256 + threadIdx.x;   // BT_*256 pairs
    const int w = idx & 255;
    const int bt = idx >> 8;
    const int b = bt / T_, t = bt - b * T_;
    const int d0 = 2 * w;
    float s0 = 0.f, s1 = 0.f;
#pragma unroll
    for (int j = 0; j < K_; j++) {
        int tt = t - (K_ - 1) + j;
        if (tt >= 0) {
            const float* row = GV + (size_t)(b * T_ + tt) * (2 * D_) + D_;
            s0 += row[d0]     * cw[d0 * K_ + j];
            s1 += row[d0 + 1] * cw[(d0 + 1) * K_ + j];
        }
    }
    float g0 = GV[(size_t)bt * (2 * D_) + d0];
    float g1 = GV[(size_t)bt * (2 * D_) + d0 + 1];
    float y0 = s0 / (1.f + expf(-g0));
    float y1 = s1 / (1.f + expf(-g1));
    unsigned hi, lo;
    split_pack(y0, y1, hi, lo);
    size_t base = (((size_t)bt * (D_ / 16) + (w >> 3)) << 4) + (w & 7);
    CG2[base] = hi; CG2[base + 8] = lo;
}

// ---------------- small projections ----------------
__global__ __launch_bounds__(256) void smallproj_kernel(
    const float* __restrict__ HN, const float* __restrict__ wg,
    const float* __restrict__ rqw, const float* __restrict__ wv,
    float* __restrict__ G, float* __restrict__ RQ, float* __restrict__ Vv)
{
    const int bt = blockIdx.x;
    const int tid = threadIdx.x;
    __shared__ float h[D_];
    h[tid] = HN[bt * D_ + tid];
    h[tid + 256] = HN[bt * D_ + tid + 256];
    __syncthreads();
    const int warp = tid >> 5, lane = tid & 31;
    for (int o = warp; o < S_ + S_ + DS_; o += 8) {
        const float* wrow;
        if (o < S_) wrow = wg + o * D_;
        else if (o < 2 * S_) wrow = rqw + (o - S_) * D_;
        else wrow = wv + (o - 2 * S_) * D_;
        float s = 0.f;
#pragma unroll
        for (int k = lane; k < D_; k += 32) s += h[k] * wrow[k];
#pragma unroll
        for (int off = 16; off > 0; off >>= 1) s += __shfl_down_sync(0xffffffffu, s, off);
        if (lane == 0) {
            if (o < S_) G[bt * S_ + o] = 1.f / (1.f + expf(-s));
            else if (o < 2 * S_) RQ[bt * S_ + (o - S_)] = s;
            else Vv[bt * DS_ + (o - 2 * S_)] = s;
        }
    }
}

// ---------------- chunked linear-recurrence scan ----------------
__global__ __launch_bounds__(256) void scan_pass1_kernel(
    const float* __restrict__ G, const float* __restrict__ Vv,
    float* __restrict__ CHA, float* __restrict__ CHB)
{
    const int idx = blockIdx.x * 256 + threadIdx.x;
    const int ds = idx % DS_;
    const int s  = (idx / DS_) % S_;
    const int c  = (idx / (DS_ * S_)) % NC_;
    const int b  = idx / (DS_ * S_ * NC_);
    float A = 1.f, Bv = 0.f;
    const int t0 = c * TC_;
    for (int t = t0; t < t0 + TC_; t++) {
        float g = G[(size_t)(b * T_ + t) * S_ + s];
        float a = 1.f - g;
        float bb = g * Vv[(size_t)(b * T_ + t) * DS_ + ds];
        A = a * A;
        Bv = a * Bv + bb;
    }
    CHB[((size_t)(b * S_ + s) * DS_ + ds) * NC_ + c] = Bv;
    if (ds == 0) CHA[(size_t)(b * S_ + s) * NC_ + c] = A;
}

__global__ __launch_bounds__(512) void scan_pass2_kernel(
    const float* __restrict__ CHA, const float* __restrict__ CHB,
    float* __restrict__ MEM, float* __restrict__ CST)
{
    const int idx = threadIdx.x;
    const int ds = idx % DS_;
    const int s  = (idx / DS_) % S_;
    const int b  = idx / (DS_ * S_);
    float st = MEM[idx];
    for (int c = 0; c < NC_; c++) {
        CST[((size_t)(b * S_ + s) * DS_ + ds) * NC_ + c] = st;
        float A = CHA[(size_t)(b * S_ + s) * NC_ + c];
        float Bv = CHB[((size_t)(b * S_ + s) * DS_ + ds) * NC_ + c];
        st = A * st + Bv;
    }
    MEM[idx] = st;
}

__global__ __launch_bounds__(256) void scan_pass3_kernel(
    const float* __restrict__ G, const float* __restrict__ Vv,
    const float* __restrict__ CST, float* __restrict__ MS)
{
    const int idx = blockIdx.x * 256 + threadIdx.x;
    const int ds = idx % DS_;
    const int s  = (idx / DS_) % S_;
    const int c  = (idx / (DS_ * S_)) % NC_;
    const int b  = idx / (DS_ * S_ * NC_);
    float m = CST[((size_t)(b * S_ + s) * DS_ + ds) * NC_ + c];
    const int t0 = c * TC_;
    for (int t = t0; t < t0 + TC_; t++) {
        float g = G[(size_t)(b * T_ + t) * S_ + s];
        float bb = g * Vv[(size_t)(b * T_ + t) * DS_ + ds];
        m = (1.f - g) * m + bb;
        MS[(size_t)(b * T_ + t) * (S_ * DS_) + s * DS_ + ds] = m;
    }
}

// ---------------- softmax read-weights * mem_stack -> split-packed ----------------
__global__ __launch_bounds__(128) void rf_split_kernel(
    const float* __restrict__ RQ, const float* __restrict__ MS, unsigned* __restrict__ RF2)
{
    const int bt = blockIdx.x;
    const int t = threadIdx.x;   // 128 pairs
    __shared__ float q[S_];
    if (t < S_) q[t] = RQ[bt * S_ + t];
    __syncthreads();
    float mx = q[0];
#pragma unroll
    for (int i = 1; i < S_; i++) mx = fmaxf(mx, q[i]);
    float den = 0.f;
#pragma unroll
    for (int i = 0; i < S_; i++) den += expf(q[i] - mx);
    const int k0 = 2 * t;
    const int s = k0 >> 5;
    float wgt = expf(q[s] - mx) / den;
    float y0 = wgt * MS[(size_t)bt * 256 + k0];
    float y1 = wgt * MS[(size_t)bt * 256 + k0 + 1];
    unsigned hi, lo;
    split_pack(y0, y1, hi, lo);
    size_t base = (((size_t)bt * 16 + (t >> 3)) << 4) + (t & 7);
    RF2[base] = hi; RF2[base + 8] = lo;
}

// ---------------- silu(gate)*up -> split-packed ----------------
__global__ __launch_bounds__(256) void silu_split_kernel(
    const float* __restrict__ UPc, unsigned* __restrict__ UP2)
{
    const int idx = blockIdx.x * 256 + threadIdx.x;   // BT_*1024 pairs
    const int bt = idx >> 10;
    const int w = idx & 1023;
    const int f0 = 2 * w;
    float a0 = UPc[(size_t)bt * 4096 + f0];
    float a1 = UPc[(size_t)bt * 4096 + f0 + 1];
    float b0 = UPc[(size_t)bt * 4096 + 2048 + f0];
    float b1 = UPc[(size_t)bt * 4096 + 2048 + f0 + 1];
    float y0 = a0 / (1.f + expf(-a0)) * b0;
    float y1 = a1 / (1.f + expf(-a1)) * b1;
    unsigned hi, lo;
    split_pack(y0, y1, hi, lo);
    size_t base = (((size_t)bt * 128 + (w >> 3)) << 4) + (w & 7);
    UP2[base] = hi; UP2[base + 8] = lo;
}

// ---------------- zero memory ----------------
__global__ void zero_mem_kernel(float* __restrict__ M)
{
    M[threadIdx.x] = 0.f;
}

// ---------------- host orchestration ----------------
static void* devptr(const void* symbol) {
    void* p = nullptr;
    cudaGetSymbolAddress(&p, symbol);
    return p;
}

static inline int cblocks(long long threads) { return (int)((threads + 255) / 256); }

extern "C" void kernel_launch(void* const* d_in, const int* in_sizes, int n_in,
                              void* d_out, int out_size)
{
    const int*   tokens    = (const int*)  d_in[0];
    const float* embed     = (const float*)d_in[1];
    const float* ln_in     = (const float*)d_in[2];
    const float* ln1       = (const float*)d_in[3];
    const float* mixer_up  = (const float*)d_in[4];
    const float* conv_w    = (const float*)d_in[5];
    const float* mixer_down= (const float*)d_in[6];
    const float* ln_mem    = (const float*)d_in[7];
    const float* wg        = (const float*)d_in[8];
    const float* wv        = (const float*)d_in[9];
    const float* rq        = (const float*)d_in[10];
    const float* ro        = (const float*)d_in[11];
    const float* ln2       = (const float*)d_in[12];
    const float* Wgf       = (const float*)d_in[13];
    const float* Wuf       = (const float*)d_in[14];
    const float* Wof       = (const float*)d_in[15];
    const float* ln_out    = (const float*)d_in[16];
    float* out = (float*)d_out;

    float* X   = (float*)devptr(d_X);
    float* HN  = (float*)devptr(d_HN);
    float* GV  = (float*)devptr(d_GV);
    float* G   = (float*)devptr(d_G);
    float* RQ  = (float*)devptr(d_RQ);
    float* Vv  = (float*)devptr(d_V);
    float* MS  = (float*)devptr(d_MS);
    float* UPc = (float*)devptr(d_UPc);
    float* MEM = (float*)devptr(d_MEM);
    float* CHA = (float*)devptr(d_CHA);
    float* CHB = (float*)devptr(d_CHB);
    float* CST = (float*)devptr(d_CST);

    unsigned* HN2 = (unsigned*)devptr(d_HN2);
    unsigned* CG2 = (unsigned*)devptr(d_CG2);
    unsigned* RF2 = (unsigned*)devptr(d_RF2);
    unsigned* UP2 = (unsigned*)devptr(d_UP2);
    unsigned* WMU = (unsigned*)devptr(d_WMU);
    unsigned* WMD = (unsigned*)devptr(d_WMD);
    unsigned* WRO = (unsigned*)devptr(d_WRO);
    unsigned* WFF = (unsigned*)devptr(d_WFF);
    unsigned* WOF = (unsigned*)devptr(d_WOF);
    unsigned* WEM = (unsigned*)devptr(d_WEM);

    // ---- weight pre-conversion (per launch; weights may change between calls) ----
    {
        int r;
        r = L_ * 2 * D_;            // mixer_up: (6144, 512)
        convert_split_kernel<<<cblocks((long long)r * (D_/2)), 256>>>(mixer_up, WMU, r, D_, r, r, 0);
        r = L_ * D_;                // mixer_down: (3072, 512)
        convert_split_kernel<<<cblocks((long long)r * (D_/2)), 256>>>(mixer_down, WMD, r, D_, r, r, 0);
        r = L_ * D_;                // ro: (3072, 256)
        convert_split_kernel<<<cblocks((long long)r * (S_*DS_/2)), 256>>>(ro, WRO, r, S_*DS_, r, r, 0);
        r = L_ * FF_;               // Wgf -> WFF rows [l*4096 .. l*4096+2047]
        convert_split_kernel<<<cblocks((long long)r * (D_/2)), 256>>>(Wgf, WFF, r, D_, FF_, 2*FF_, 0);
        r = L_ * FF_;               // Wuf -> WFF rows [l*4096+2048 ..]
        convert_split_kernel<<<cblocks((long long)r * (D_/2)), 256>>>(Wuf, WFF, r, D_, FF_, 2*FF_, FF_);
        r = L_ * D_;                // Wof: (3072, 2048)
        convert_split_kernel<<<cblocks((long long)r * (FF_/2)), 256>>>(Wof, WOF, r, FF_, r, r, 0);
        r = V_;                     // embed: (32000, 512)
        convert_split_kernel<<<cblocks((long long)r * (D_/2)), 256>>>(embed, WEM, r, D_, r, r, 0);
    }

    const int scanThreads = B_ * S_ * DS_ * NC_;   // 16384

    zero_mem_kernel<<<1, B_ * S_ * DS_>>>(MEM);
    embed_norm_kernel<<<BT_, 256>>>(tokens, embed, ln_in, X);

    for (int i = 0; i < L_; i++) {
        const float* ln1_i = ln1 + i * D_;
        const float* cw_i  = conv_w + (size_t)i * D_ * K_;
        const float* lnm_i = ln_mem + i * D_;
        const float* wg_i  = wg + (size_t)i * S_ * D_;
        const float* wv_i  = wv + (size_t)i * DS_ * D_;
        const float* rq_i  = rq + (size_t)i * S_ * D_;
        const float* ln2_i = ln2 + i * D_;

        const unsigned* wmu_i = WMU + (size_t)i * 2 * D_ * D_;
        const unsigned* wmd_i = WMD + (size_t)i * D_ * D_;
        const unsigned* wro_i = WRO + (size_t)i * D_ * S_ * DS_;
        const unsigned* wff_i = WFF + (size_t)i * 2 * FF_ * D_;
        const unsigned* wof_i = WOF + (size_t)i * D_ * FF_;

        // mixer branch
        rmsnorm_split_kernel<<<BT_, 256>>>(X, ln1_i, HN2);
        bsgemm_kernel<false><<<dim3(2 * D_ / 128, BT_ / 128), 256>>>(
            HN2, wmu_i, nullptr, GV, BT_, 2 * D_, D_ / 16);
        conv_gate_split_kernel<<<BT_, 256>>>(GV, cw_i, CG2);
        bsgemm_kernel<true><<<dim3(D_ / 128, BT_ / 128), 256>>>(
            CG2, wmd_i, X, X, BT_, D_, D_ / 16);

        // story memory branch
        rmsnorm_kernel<<<BT_, 256>>>(X, lnm_i, HN);
        smallproj_kernel<<<BT_, 256>>>(HN, wg_i, rq_i, wv_i, G, RQ, Vv);
        scan_pass1_kernel<<<scanThreads / 256, 256>>>(G, Vv, CHA, CHB);
        scan_pass2_kernel<<<1, B_ * S_ * DS_>>>(CHA, CHB, MEM, CST);
        scan_pass3_kernel<<<scanThreads / 256, 256>>>(G, Vv, CST, MS);
        rf_split_kernel<<<BT_, 128>>>(RQ, MS, RF2);
        bsgemm_kernel<true><<<dim3(D_ / 128, BT_ / 128), 256>>>(
            RF2, wro_i, X, X, BT_, D_, S_ * DS_ / 16);

        // FFN branch (fused gate+up GEMM, N = 4096)
        rmsnorm_split_kernel<<<BT_, 256>>>(X, ln2_i, HN2);
        bsgemm_kernel<false><<<dim3(2 * FF_ / 128, BT_ / 128), 256>>>(
            HN2, wff_i, nullptr, UPc, BT_, 2 * FF_, D_ / 16);
        silu_split_kernel<<<cblocks((long long)BT_ * (FF_ / 2)), 256>>>(UPc, UP2);
        bsgemm_kernel<true><<<dim3(D_ / 128, BT_ / 128), 256>>>(
            UP2, wof_i, X, X, BT_, D_, FF_ / 16);
    }

    // tied head
    rmsnorm_split_kernel<<<BT_, 256>>>(X, ln_out, HN2);
    bsgemm_kernel<false><<<dim3(V_ / 128, BT_ / 128), 256>>>(
        HN2, WEM, nullptr, out, BT_, V_, D_ / 16);
}

// round 6
// speedup vs baseline: 1.0159x; 1.0159x over previous
#include <cuda_runtime.h>
#include <cuda_bf16.h>
#include <stdint.h>
#include <math.h>

// ---------------- problem constants ----------------
#define V_  32000
#define D_  512
#define L_  6
#define FF_ 2048
#define T_  2048
#define B_  2
#define S_  8
#define DS_ 32
#define K_  15

#define BT_ (B_ * T_)          // 4096 tokens
#define NC_ 32                 // scan chunks
#define TC_ (T_ / NC_)         // 64 steps per chunk

// ---------------- device scratch (no allocations allowed) ----------------
__device__ float d_X  [BT_ * D_];
__device__ float d_HN [BT_ * D_];
__device__ float d_GV [BT_ * 2 * D_];
__device__ float d_G  [BT_ * S_];
__device__ float d_RQ [BT_ * S_];
__device__ float d_V  [BT_ * DS_];
__device__ float d_MS [BT_ * S_ * DS_];
__device__ float d_UPc[BT_ * 2 * FF_];
__device__ float d_MEM[B_ * S_ * DS_];
__device__ float d_CHA[B_ * S_ * NC_];
__device__ float d_CHB[B_ * S_ * DS_ * NC_];
__device__ float d_CST[B_ * S_ * DS_ * NC_];

// split-bf16 packed operands, layout per row: [k32 chunk][16 hi words | 16 lo words]
// word = 2 bf16 (elements 2j low16, 2j+1 high16).
__device__ unsigned d_HN2[BT_ * D_];             // K=512
__device__ unsigned d_CG2[BT_ * D_];             // K=512
__device__ unsigned d_RF2[BT_ * S_ * DS_];       // K=256
__device__ unsigned d_UP2[BT_ * FF_];            // K=2048
__device__ unsigned d_WMU[L_ * 2 * D_ * D_];
__device__ unsigned d_WMD[L_ * D_ * D_];
__device__ unsigned d_WRO[L_ * D_ * S_ * DS_];
__device__ unsigned d_WFF[L_ * 2 * FF_ * D_];    // rows 0..2047=Wgf, 2048..=Wuf per layer
__device__ unsigned d_WOF[L_ * D_ * FF_];
__device__ unsigned d_WEM[V_ * D_];

// ---------------- bf16 split helpers ----------------
__device__ __forceinline__ unsigned pack_hilo(float x0, float x1, unsigned& lo)
{
    __nv_bfloat16 h0 = __float2bfloat16_rn(x0);
    __nv_bfloat16 h1 = __float2bfloat16_rn(x1);
    float l0f = x0 - __bfloat162float(h0);
    float l1f = x1 - __bfloat162float(h1);
    __nv_bfloat16 l0 = __float2bfloat16_rn(l0f);
    __nv_bfloat16 l1 = __float2bfloat16_rn(l1f);
    lo = (unsigned)__bfloat16_as_ushort(l0) | ((unsigned)__bfloat16_as_ushort(l1) << 16);
    return (unsigned)__bfloat16_as_ushort(h0) | ((unsigned)__bfloat16_as_ushort(h1) << 16);
}

__device__ __forceinline__ void mma_bf16(float* c, const unsigned* a, unsigned b0, unsigned b1)
{
    asm volatile(
        "mma.sync.aligned.m16n8k16.row.col.f32.bf16.bf16.f32 "
        "{%0,%1,%2,%3}, {%4,%5,%6,%7}, {%8,%9}, {%0,%1,%2,%3};"
        : "+f"(c[0]), "+f"(c[1]), "+f"(c[2]), "+f"(c[3])
        : "r"(a[0]), "r"(a[1]), "r"(a[2]), "r"(a[3]), "r"(b0), "r"(b1));
}

__device__ __forceinline__ void ldsm4(unsigned& r0, unsigned& r1, unsigned& r2, unsigned& r3,
                                      unsigned saddr)
{
    asm volatile("ldmatrix.sync.aligned.m8n8.x4.shared.b16 {%0,%1,%2,%3}, [%4];"
                 : "=r"(r0), "=r"(r1), "=r"(r2), "=r"(r3) : "r"(saddr));
}

__device__ __forceinline__ void cp16(unsigned saddr, const void* g)
{
    asm volatile("cp.async.cg.shared.global [%0], [%1], 16;" :: "r"(saddr), "l"(g));
}

// ---------------- split-bf16 tensor GEMM: C[M,N] = A @ W^T (+R) ----------------
// 128x128 tile, 8 warps (2x4), 64x32 warp tile, k-chunk 32, double-buffered cp.async,
// ldmatrix fragment loads, 3-term split-bf16 (hi*hi + lo*hi + hi*lo).
#define TW_ 20                   // padded row stride (words); banks 20r mod 32 distinct
#define TILE_W_ (128 * TW_)      // 2560 words per tile
#define STAGE_W_ (4 * TILE_W_)   // Ahi,Alo,Bhi,Blo
#define SMEM_B_ (2 * STAGE_W_ * 4)   // 81920 bytes

template<bool RES>
__global__ __launch_bounds__(256, 2)
void bsgemm_kernel(const unsigned* __restrict__ A, const unsigned* __restrict__ W,
                   const float* __restrict__ R, float* __restrict__ C,
                   int M, int N, int KC)   // KC = K/32
{
    extern __shared__ unsigned sm[];
    const unsigned sbase = (unsigned)__cvta_generic_to_shared(sm);
    const int tid = threadIdx.x, wid = tid >> 5, lane = tid & 31;
    const int grp = lane >> 2, kin = lane & 3;
    const int wm = (wid & 1) * 64, wn = (wid >> 1) * 32;
    const int row0 = blockIdx.y * 128, col0 = blockIdx.x * 128;

    // per-thread load slots: 2 cp.async per tile (4 tiles) per stage
    const int cr0 = (tid * 2) >> 2,     cj0 = (tid * 2) & 3;
    const int cr1 = (tid * 2 + 1) >> 2, cj1 = (tid * 2 + 1) & 3;

    float acc[4][4][4];
#pragma unroll
    for (int i = 0; i < 4; i++)
#pragma unroll
        for (int j = 0; j < 4; j++)
#pragma unroll
            for (int r = 0; r < 4; r++) acc[i][j][r] = 0.f;

    // ---- stage loader ----
    auto load_stage = [&](int c, int st) {
        const unsigned sb = sbase + (unsigned)(st * STAGE_W_) * 4u;
        // slot 0
        {
            const size_t ga = ((size_t)(row0 + cr0) * KC + c) * 32 + cj0 * 4;
            const size_t gb = ((size_t)(col0 + cr0) * KC + c) * 32 + cj0 * 4;
            const unsigned so = (unsigned)(cr0 * TW_ + cj0 * 4) * 4u;
            cp16(sb + so,                         A + ga);        // A hi
            cp16(sb + TILE_W_ * 4u + so,          A + ga + 16);   // A lo
            cp16(sb + 2u * TILE_W_ * 4u + so,     W + gb);        // B hi
            cp16(sb + 3u * TILE_W_ * 4u + so,     W + gb + 16);   // B lo
        }
        // slot 1
        {
            const size_t ga = ((size_t)(row0 + cr1) * KC + c) * 32 + cj1 * 4;
            const size_t gb = ((size_t)(col0 + cr1) * KC + c) * 32 + cj1 * 4;
            const unsigned so = (unsigned)(cr1 * TW_ + cj1 * 4) * 4u;
            cp16(sb + so,                         A + ga);
            cp16(sb + TILE_W_ * 4u + so,          A + ga + 16);
            cp16(sb + 2u * TILE_W_ * 4u + so,     W + gb);
            cp16(sb + 3u * TILE_W_ * 4u + so,     W + gb + 16);
        }
    };

    load_stage(0, 0);
    asm volatile("cp.async.commit_group;" ::: "memory");

    // ldmatrix lane addressing components
    const int lrow_add = (lane & 7) + ((lane >> 3) & 1) * 8;
    const int lword_add = (lane >> 4) * 4;

    for (int c = 0; c < KC; c++) {
        if (c + 1 < KC) {
            load_stage(c + 1, (c + 1) & 1);
            asm volatile("cp.async.commit_group;" ::: "memory");
            asm volatile("cp.async.wait_group 1;" ::: "memory");
        } else {
            asm volatile("cp.async.wait_group 0;" ::: "memory");
        }
        __syncthreads();

        const unsigned sb = sbase + (unsigned)((c & 1) * STAGE_W_) * 4u;
        const unsigned aHi = sb;
        const unsigned aLo = sb + TILE_W_ * 4u;
        const unsigned bHi = sb + 2u * TILE_W_ * 4u;
        const unsigned bLo = sb + 3u * TILE_W_ * 4u;

#pragma unroll
        for (int s16 = 0; s16 < 2; s16++) {
            const int kw = s16 * 8 + lword_add;
            unsigned ah[4][4], al[4][4], bh[4][2], bl[4][2];
#pragma unroll
            for (int i = 0; i < 4; i++) {
                const unsigned off = (unsigned)((wm + i * 16 + lrow_add) * TW_ + kw) * 4u;
                ldsm4(ah[i][0], ah[i][1], ah[i][2], ah[i][3], aHi + off);
                ldsm4(al[i][0], al[i][1], al[i][2], al[i][3], aLo + off);
            }
#pragma unroll
            for (int jj = 0; jj < 2; jj++) {
                const unsigned off = (unsigned)((wn + jj * 16 + lrow_add) * TW_ + kw) * 4u;
                unsigned q0, q1, q2, q3;
                ldsm4(q0, q1, q2, q3, bHi + off);
                bh[jj * 2][0] = q0; bh[jj * 2 + 1][0] = q1;
                bh[jj * 2][1] = q2; bh[jj * 2 + 1][1] = q3;
                ldsm4(q0, q1, q2, q3, bLo + off);
                bl[jj * 2][0] = q0; bl[jj * 2 + 1][0] = q1;
                bl[jj * 2][1] = q2; bl[jj * 2 + 1][1] = q3;
            }
#pragma unroll
            for (int j = 0; j < 4; j++)
#pragma unroll
                for (int i = 0; i < 4; i++) {
                    mma_bf16(acc[i][j], ah[i], bh[j][0], bh[j][1]);
                    mma_bf16(acc[i][j], al[i], bh[j][0], bh[j][1]);
                    mma_bf16(acc[i][j], ah[i], bl[j][0], bl[j][1]);
                }
        }
        __syncthreads();
    }

    // epilogue
    const int orow0 = row0 + wm + grp;
    const int ocol0 = col0 + wn + 2 * kin;
#pragma unroll
    for (int i = 0; i < 4; i++) {
#pragma unroll
        for (int j = 0; j < 4; j++) {
            const size_t o0 = (size_t)(orow0 + i * 16) * N + ocol0 + j * 8;
            const size_t o1 = (size_t)(orow0 + i * 16 + 8) * N + ocol0 + j * 8;
            float2 v0 = make_float2(acc[i][j][0], acc[i][j][1]);
            float2 v1 = make_float2(acc[i][j][2], acc[i][j][3]);
            if (RES) {
                float2 r0 = *reinterpret_cast<const float2*>(R + o0);
                float2 r1 = *reinterpret_cast<const float2*>(R + o1);
                v0.x += r0.x; v0.y += r0.y;
                v1.x += r1.x; v1.y += r1.y;
            }
            *reinterpret_cast<float2*>(C + o0) = v0;
            *reinterpret_cast<float2*>(C + o1) = v1;
        }
    }
}

// ---------------- weight converter -> packed split layout (k32 chunks) ----------------
__global__ __launch_bounds__(256) void convert_split_kernel(
    const float* __restrict__ src, unsigned* __restrict__ dst,
    int nRows, int K, int group, int dstride, int dbase)
{
    int kp2 = K >> 1;
    int idx = blockIdx.x * 256 + threadIdx.x;
    if (idx >= nRows * kp2) return;
    int n = idx / kp2, p = idx - n * kp2;
    float x = src[(size_t)n * K + 2 * p];
    float y = src[(size_t)n * K + 2 * p + 1];
    unsigned lo, hi = pack_hilo(x, y, lo);
    int dn = (n / group) * dstride + dbase + (n % group);
    size_t base = ((size_t)dn * (K >> 5) + (p >> 4)) * 32 + (p & 15);
    dst[base] = hi;
    dst[base + 16] = lo;
}

// ---------------- embed gather + rmsnorm(ln_in) -> fp32 X ----------------
__global__ __launch_bounds__(256) void embed_norm_kernel(
    const int* __restrict__ tokens, const float* __restrict__ embed,
    const float* __restrict__ w, float* __restrict__ out)
{
    const int bt = blockIdx.x;
    const int tid = threadIdx.x;
    const int tok = tokens[bt];
    const float* row = embed + (size_t)tok * D_;
    float x0 = row[tid], x1 = row[tid + 256];
    __shared__ float red[256];
    red[tid] = x0 * x0 + x1 * x1;
    __syncthreads();
    for (int s = 128; s > 0; s >>= 1) {
        if (tid < s) red[tid] += red[tid + s];
        __syncthreads();
    }
    float scale = rsqrtf(red[0] / (float)D_ + 1e-6f);
    out[bt * D_ + tid]       = x0 * scale * w[tid];
    out[bt * D_ + tid + 256] = x1 * scale * w[tid + 256];
}

// ---------------- rmsnorm -> fp32 (story-memory branch) ----------------
__global__ __launch_bounds__(256) void rmsnorm_kernel(
    const float* __restrict__ X, const float* __restrict__ w, float* __restrict__ O)
{
    const int bt = blockIdx.x;
    const int tid = threadIdx.x;
    float x0 = X[bt * D_ + tid], x1 = X[bt * D_ + tid + 256];
    __shared__ float red[256];
    red[tid] = x0 * x0 + x1 * x1;
    __syncthreads();
    for (int s = 128; s > 0; s >>= 1) {
        if (tid < s) red[tid] += red[tid + s];
        __syncthreads();
    }
    float scale = rsqrtf(red[0] / (float)D_ + 1e-6f);
    O[bt * D_ + tid]       = x0 * scale * w[tid];
    O[bt * D_ + tid + 256] = x1 * scale * w[tid + 256];
}

// ---------------- rmsnorm -> split-packed (K=512) ----------------
__global__ __launch_bounds__(256) void rmsnorm_split_kernel(
    const float* __restrict__ X, const float* __restrict__ w, unsigned* __restrict__ O)
{
    const int bt = blockIdx.x;
    const int t = threadIdx.x;
    float x0 = X[(size_t)bt * D_ + 2 * t];
    float x1 = X[(size_t)bt * D_ + 2 * t + 1];
    __shared__ float red[256];
    red[t] = x0 * x0 + x1 * x1;
    __syncthreads();
    for (int s = 128; s > 0; s >>= 1) {
        if (t < s) red[t] += red[t + s];
        __syncthreads();
    }
    float sc = rsqrtf(red[0] / (float)D_ + 1e-6f);
    float y0 = x0 * sc * w[2 * t], y1 = x1 * sc * w[2 * t + 1];
    unsigned lo, hi = pack_hilo(y0, y1, lo);
    size_t base = ((size_t)bt * 16 + (t >> 4)) * 32 + (t & 15);
    O[base] = hi; O[base + 16] = lo;
}

// ---------------- causal depthwise conv + gate -> split-packed (K=512) ----------------
__global__ __launch_bounds__(256) void conv_gate_split_kernel(
    const float* __restrict__ GV, const float* __restrict__ cw, unsigned* __restrict__ CG2)
{
    const int idx = blockIdx.x * 256 + threadIdx.x;
    const int w = idx & 255;
    const int bt = idx >> 8;
    const int b = bt / T_, t = bt - b * T_;
    const int d0 = 2 * w;
    float s0 = 0.f, s1 = 0.f;
#pragma unroll
    for (int j = 0; j < K_; j++) {
        int tt = t - (K_ - 1) + j;
        if (tt >= 0) {
            const float* row = GV + (size_t)(b * T_ + tt) * (2 * D_) + D_;
            s0 += row[d0]     * cw[d0 * K_ + j];
            s1 += row[d0 + 1] * cw[(d0 + 1) * K_ + j];
        }
    }
    float g0 = GV[(size_t)bt * (2 * D_) + d0];
    float g1 = GV[(size_t)bt * (2 * D_) + d0 + 1];
    float y0 = s0 / (1.f + expf(-g0));
    float y1 = s1 / (1.f + expf(-g1));
    unsigned lo, hi = pack_hilo(y0, y1, lo);
    size_t base = ((size_t)bt * 16 + (w >> 4)) * 32 + (w & 15);
    CG2[base] = hi; CG2[base + 16] = lo;
}

// ---------------- small projections ----------------
__global__ __launch_bounds__(256) void smallproj_kernel(
    const float* __restrict__ HN, const float* __restrict__ wg,
    const float* __restrict__ rqw, const float* __restrict__ wv,
    float* __restrict__ G, float* __restrict__ RQ, float* __restrict__ Vv)
{
    const int bt = blockIdx.x;
    const int tid = threadIdx.x;
    __shared__ float h[D_];
    h[tid] = HN[bt * D_ + tid];
    h[tid + 256] = HN[bt * D_ + tid + 256];
    __syncthreads();
    const int warp = tid >> 5, lane = tid & 31;
    for (int o = warp; o < S_ + S_ + DS_; o += 8) {
        const float* wrow;
        if (o < S_) wrow = wg + o * D_;
        else if (o < 2 * S_) wrow = rqw + (o - S_) * D_;
        else wrow = wv + (o - 2 * S_) * D_;
        float s = 0.f;
#pragma unroll
        for (int k = lane; k < D_; k += 32) s += h[k] * wrow[k];
#pragma unroll
        for (int off = 16; off > 0; off >>= 1) s += __shfl_down_sync(0xffffffffu, s, off);
        if (lane == 0) {
            if (o < S_) G[bt * S_ + o] = 1.f / (1.f + expf(-s));
            else if (o < 2 * S_) RQ[bt * S_ + (o - S_)] = s;
            else Vv[bt * DS_ + (o - 2 * S_)] = s;
        }
    }
}

// ---------------- chunked linear-recurrence scan ----------------
__global__ __launch_bounds__(256) void scan_pass1_kernel(
    const float* __restrict__ G, const float* __restrict__ Vv,
    float* __restrict__ CHA, float* __restrict__ CHB)
{
    const int idx = blockIdx.x * 256 + threadIdx.x;
    const int ds = idx % DS_;
    const int s  = (idx / DS_) % S_;
    const int c  = (idx / (DS_ * S_)) % NC_;
    const int b  = idx / (DS_ * S_ * NC_);
    float A = 1.f, Bv = 0.f;
    const int t0 = c * TC_;
    for (int t = t0; t < t0 + TC_; t++) {
        float g = G[(size_t)(b * T_ + t) * S_ + s];
        float a = 1.f - g;
        float bb = g * Vv[(size_t)(b * T_ + t) * DS_ + ds];
        A = a * A;
        Bv = a * Bv + bb;
    }
    CHB[((size_t)(b * S_ + s) * DS_ + ds) * NC_ + c] = Bv;
    if (ds == 0) CHA[(size_t)(b * S_ + s) * NC_ + c] = A;
}

__global__ __launch_bounds__(512) void scan_pass2_kernel(
    const float* __restrict__ CHA, const float* __restrict__ CHB,
    float* __restrict__ MEM, float* __restrict__ CST)
{
    const int idx = threadIdx.x;
    const int ds = idx % DS_;
    const int s  = (idx / DS_) % S_;
    const int b  = idx / (DS_ * S_);
    float st = MEM[idx];
    for (int c = 0; c < NC_; c++) {
        CST[((size_t)(b * S_ + s) * DS_ + ds) * NC_ + c] = st;
        float A = CHA[(size_t)(b * S_ + s) * NC_ + c];
        float Bv = CHB[((size_t)(b * S_ + s) * DS_ + ds) * NC_ + c];
        st = A * st + Bv;
    }
    MEM[idx] = st;
}

__global__ __launch_bounds__(256) void scan_pass3_kernel(
    const float* __restrict__ G, const float* __restrict__ Vv,
    const float* __restrict__ CST, float* __restrict__ MS)
{
    const int idx = blockIdx.x * 256 + threadIdx.x;
    const int ds = idx % DS_;
    const int s  = (idx / DS_) % S_;
    const int c  = (idx / (DS_ * S_)) % NC_;
    const int b  = idx / (DS_ * S_ * NC_);
    float m = CST[((size_t)(b * S_ + s) * DS_ + ds) * NC_ + c];
    const int t0 = c * TC_;
    for (int t = t0; t < t0 + TC_; t++) {
        float g = G[(size_t)(b * T_ + t) * S_ + s];
        float bb = g * Vv[(size_t)(b * T_ + t) * DS_ + ds];
        m = (1.f - g) * m + bb;
        MS[(size_t)(b * T_ + t) * (S_ * DS_) + s * DS_ + ds] = m;
    }
}

// ---------------- softmax read-weights * mem_stack -> split-packed (K=256) ----------------
__global__ __launch_bounds__(128) void rf_split_kernel(
    const float* __restrict__ RQ, const float* __restrict__ MS, unsigned* __restrict__ RF2)
{
    const int bt = blockIdx.x;
    const int t = threadIdx.x;
    __shared__ float q[S_];
    if (t < S_) q[t] = RQ[bt * S_ + t];
    __syncthreads();
    float mx = q[0];
#pragma unroll
    for (int i = 1; i < S_; i++) mx = fmaxf(mx, q[i]);
    float den = 0.f;
#pragma unroll
    for (int i = 0; i < S_; i++) den += expf(q[i] - mx);
    const int k0 = 2 * t;
    const int s = k0 >> 5;
    float wgt = expf(q[s] - mx) / den;
    float y0 = wgt * MS[(size_t)bt * 256 + k0];
    float y1 = wgt * MS[(size_t)bt * 256 + k0 + 1];
    unsigned lo, hi = pack_hilo(y0, y1, lo);
    size_t base = ((size_t)bt * 8 + (t >> 4)) * 32 + (t & 15);
    RF2[base] = hi; RF2[base + 16] = lo;
}

// ---------------- silu(gate)*up -> split-packed (K=2048) ----------------
__global__ __launch_bounds__(256) void silu_split_kernel(
    const float* __restrict__ UPc, unsigned* __restrict__ UP2)
{
    const int idx = blockIdx.x * 256 + threadIdx.x;
    const int bt = idx >> 10;
    const int w = idx & 1023;
    const int f0 = 2 * w;
    float a0 = UPc[(size_t)bt * 4096 + f0];
    float a1 = UPc[(size_t)bt * 4096 + f0 + 1];
    float b0 = UPc[(size_t)bt * 4096 + 2048 + f0];
    float b1 = UPc[(size_t)bt * 4096 + 2048 + f0 + 1];
    float y0 = a0 / (1.f + expf(-a0)) * b0;
    float y1 = a1 / (1.f + expf(-a1)) * b1;
    unsigned lo, hi = pack_hilo(y0, y1, lo);
    size_t base = ((size_t)bt * 64 + (w >> 4)) * 32 + (w & 15);
    UP2[base] = hi; UP2[base + 16] = lo;
}

// ---------------- zero memory ----------------
__global__ void zero_mem_kernel(float* __restrict__ M)
{
    M[threadIdx.x] = 0.f;
}

// ---------------- host orchestration ----------------
static void* devptr(const void* symbol) {
    void* p = nullptr;
    cudaGetSymbolAddress(&p, symbol);
    return p;
}

static inline int cblocks(long long threads) { return (int)((threads + 255) / 256); }

extern "C" void kernel_launch(void* const* d_in, const int* in_sizes, int n_in,
                              void* d_out, int out_size)
{
    const int*   tokens    = (const int*)  d_in[0];
    const float* embed     = (const float*)d_in[1];
    const float* ln_in     = (const float*)d_in[2];
    const float* ln1       = (const float*)d_in[3];
    const float* mixer_up  = (const float*)d_in[4];
    const float* conv_w    = (const float*)d_in[5];
    const float* mixer_down= (const float*)d_in[6];
    const float* ln_mem    = (const float*)d_in[7];
    const float* wg        = (const float*)d_in[8];
    const float* wv        = (const float*)d_in[9];
    const float* rq        = (const float*)d_in[10];
    const float* ro        = (const float*)d_in[11];
    const float* ln2       = (const float*)d_in[12];
    const float* Wgf       = (const float*)d_in[13];
    const float* Wuf       = (const float*)d_in[14];
    const float* Wof       = (const float*)d_in[15];
    const float* ln_out    = (const float*)d_in[16];
    float* out = (float*)d_out;

    float* X   = (float*)devptr(d_X);
    float* HN  = (float*)devptr(d_HN);
    float* GV  = (float*)devptr(d_GV);
    float* G   = (float*)devptr(d_G);
    float* RQ  = (float*)devptr(d_RQ);
    float* Vv  = (float*)devptr(d_V);
    float* MS  = (float*)devptr(d_MS);
    float* UPc = (float*)devptr(d_UPc);
    float* MEM = (float*)devptr(d_MEM);
    float* CHA = (float*)devptr(d_CHA);
    float* CHB = (float*)devptr(d_CHB);
    float* CST = (float*)devptr(d_CST);

    unsigned* HN2 = (unsigned*)devptr(d_HN2);
    unsigned* CG2 = (unsigned*)devptr(d_CG2);
    unsigned* RF2 = (unsigned*)devptr(d_RF2);
    unsigned* UP2 = (unsigned*)devptr(d_UP2);
    unsigned* WMU = (unsigned*)devptr(d_WMU);
    unsigned* WMD = (unsigned*)devptr(d_WMD);
    unsigned* WRO = (unsigned*)devptr(d_WRO);
    unsigned* WFF = (unsigned*)devptr(d_WFF);
    unsigned* WOF = (unsigned*)devptr(d_WOF);
    unsigned* WEM = (unsigned*)devptr(d_WEM);

    cudaFuncSetAttribute(bsgemm_kernel<false>, cudaFuncAttributeMaxDynamicSharedMemorySize, SMEM_B_);
    cudaFuncSetAttribute(bsgemm_kernel<true>,  cudaFuncAttributeMaxDynamicSharedMemorySize, SMEM_B_);

    // ---- weight pre-conversion ----
    {
        int r;
        r = L_ * 2 * D_;
        convert_split_kernel<<<cblocks((long long)r * (D_/2)), 256>>>(mixer_up, WMU, r, D_, r, r, 0);
        r = L_ * D_;
        convert_split_kernel<<<cblocks((long long)r * (D_/2)), 256>>>(mixer_down, WMD, r, D_, r, r, 0);
        r = L_ * D_;
        convert_split_kernel<<<cblocks((long long)r * (S_*DS_/2)), 256>>>(ro, WRO, r, S_*DS_, r, r, 0);
        r = L_ * FF_;
        convert_split_kernel<<<cblocks((long long)r * (D_/2)), 256>>>(Wgf, WFF, r, D_, FF_, 2*FF_, 0);
        r = L_ * FF_;
        convert_split_kernel<<<cblocks((long long)r * (D_/2)), 256>>>(Wuf, WFF, r, D_, FF_, 2*FF_, FF_);
        r = L_ * D_;
        convert_split_kernel<<<cblocks((long long)r * (FF_/2)), 256>>>(Wof, WOF, r, FF_, r, r, 0);
        r = V_;
        convert_split_kernel<<<cblocks((long long)r * (D_/2)), 256>>>(embed, WEM, r, D_, r, r, 0);
    }

    const int scanThreads = B_ * S_ * DS_ * NC_;   // 16384

    zero_mem_kernel<<<1, B_ * S_ * DS_>>>(MEM);
    embed_norm_kernel<<<BT_, 256>>>(tokens, embed, ln_in, X);

    for (int i = 0; i < L_; i++) {
        const float* ln1_i = ln1 + i * D_;
        const float* cw_i  = conv_w + (size_t)i * D_ * K_;
        const float* lnm_i = ln_mem + i * D_;
        const float* wg_i  = wg + (size_t)i * S_ * D_;
        const float* wv_i  = wv + (size_t)i * DS_ * D_;
        const float* rq_i  = rq + (size_t)i * S_ * D_;
        const float* ln2_i = ln2 + i * D_;

        const unsigned* wmu_i = WMU + (size_t)i * 2 * D_ * D_;
        const unsigned* wmd_i = WMD + (size_t)i * D_ * D_;
        const unsigned* wro_i = WRO + (size_t)i * D_ * S_ * DS_;
        const unsigned* wff_i = WFF + (size_t)i * 2 * FF_ * D_;
        const unsigned* wof_i = WOF + (size_t)i * D_ * FF_;

        // mixer branch
        rmsnorm_split_kernel<<<BT_, 256>>>(X, ln1_i, HN2);
        bsgemm_kernel<false><<<dim3(2 * D_ / 128, BT_ / 128), 256, SMEM_B_>>>(
            HN2, wmu_i, nullptr, GV, BT_, 2 * D_, D_ / 32);
        conv_gate_split_kernel<<<BT_, 256>>>(GV, cw_i, CG2);
        bsgemm_kernel<true><<<dim3(D_ / 128, BT_ / 128), 256, SMEM_B_>>>(
            CG2, wmd_i, X, X, BT_, D_, D_ / 32);

        // story memory branch
        rmsnorm_kernel<<<BT_, 256>>>(X, lnm_i, HN);
        smallproj_kernel<<<BT_, 256>>>(HN, wg_i, rq_i, wv_i, G, RQ, Vv);
        scan_pass1_kernel<<<scanThreads / 256, 256>>>(G, Vv, CHA, CHB);
        scan_pass2_kernel<<<1, B_ * S_ * DS_>>>(CHA, CHB, MEM, CST);
        scan_pass3_kernel<<<scanThreads / 256, 256>>>(G, Vv, CST, MS);
        rf_split_kernel<<<BT_, 128>>>(RQ, MS, RF2);
        bsgemm_kernel<true><<<dim3(D_ / 128, BT_ / 128), 256, SMEM_B_>>>(
            RF2, wro_i, X, X, BT_, D_, S_ * DS_ / 32);

        // FFN branch (fused gate+up GEMM, N = 4096)
        rmsnorm_split_kernel<<<BT_, 256>>>(X, ln2_i, HN2);
        bsgemm_kernel<false><<<dim3(2 * FF_ / 128, BT_ / 128), 256, SMEM_B_>>>(
            HN2, wff_i, nullptr, UPc, BT_, 2 * FF_, D_ / 32);
        silu_split_kernel<<<cblocks((long long)BT_ * (FF_ / 2)), 256>>>(UPc, UP2);
        bsgemm_kernel<true><<<dim3(D_ / 128, BT_ / 128), 256, SMEM_B_>>>(
            UP2, wof_i, X, X, BT_, D_, FF_ / 32);
    }

    // tied head
    rmsnorm_split_kernel<<<BT_, 256>>>(X, ln_out, HN2);
    bsgemm_kernel<false><<<dim3(V_ / 128, BT_ / 128), 256, SMEM_B_>>>(
        HN2, WEM, nullptr, out, BT_, V_, D_ / 32);
}